// round 1
// baseline (speedup 1.0000x reference)
#include <cuda_runtime.h>

// Newton-Schulz orthogonalization, X in R^{2048 x 512}, fp32.
//   loop (<=20): G = X^T X ; res = ||I - G||_F^2 ; if (k>=1 && res<=EPS) stop ;
//                X = X (1.5 I - 0.5 G)
// Device-side early stop via g_done flag (graph-capturable, deterministic).

#define D_DIM 2048
#define M_DIM 512
#define NSTEPS 20
#define EPS_F 1e-6f
#define SPLITK 8
#define KC (D_DIM / SPLITK)   // 256

__device__ float g_X [D_DIM * M_DIM];          // current iterate
__device__ float g_X2[D_DIM * M_DIM];          // update target
__device__ float g_Gp[SPLITK][M_DIM * M_DIM];  // split-K gram partials
__device__ float g_G [M_DIM * M_DIM];          // gram
__device__ float g_rpart[256];                 // residual block partials
__device__ int   g_done;

// ---------------------------------------------------------------- init
__global__ void __launch_bounds__(256) init_kernel(const float* __restrict__ x) {
    int idx = blockIdx.x * blockDim.x + threadIdx.x;
    const float4* src = (const float4*)x;
    float4* dst = (float4*)g_X;
    const int n4 = D_DIM * M_DIM / 4;
    for (int i = idx; i < n4; i += gridDim.x * blockDim.x) dst[i] = src[i];
    if (idx == 0) g_done = 0;
}

// ---------------------------------------------------------------- gram: Gp[z] = X^T X (k-slice)
// grid (4,4,SPLITK): 128x128 output tile, K-chunk 256. 256 thr, 8x8 per thread.
__global__ void __launch_bounds__(256) gram_kernel() {
    if (g_done) return;
    __shared__ float As[16][128];
    __shared__ float Bs[16][128];
    const int i0 = blockIdx.x * 128;
    const int j0 = blockIdx.y * 128;
    const int k0 = blockIdx.z * KC;
    const int tid = threadIdx.x;
    const int tx = tid & 15;
    const int ty = tid >> 4;

    float acc[8][8];
#pragma unroll
    for (int u = 0; u < 8; u++)
#pragma unroll
        for (int v = 0; v < 8; v++) acc[u][v] = 0.f;

    for (int kc = 0; kc < KC; kc += 16) {
#pragma unroll
        for (int l = 0; l < 2; l++) {
            int id = tid + l * 256;          // 0..511 over 16 rows x 32 float4
            int r  = id >> 5;
            int c  = (id & 31) << 2;
            const float* rowp = &g_X[(size_t)(k0 + kc + r) * M_DIM];
            float4 a = *(const float4*)&rowp[i0 + c];
            float4 b = *(const float4*)&rowp[j0 + c];
            *(float4*)&As[r][c] = a;
            *(float4*)&Bs[r][c] = b;
        }
        __syncthreads();
#pragma unroll
        for (int kk = 0; kk < 16; kk++) {
            float a[8], b[8];
#pragma unroll
            for (int u = 0; u < 8; u++) a[u] = As[kk][ty * 8 + u];
#pragma unroll
            for (int v = 0; v < 8; v++) b[v] = Bs[kk][tx * 8 + v];
#pragma unroll
            for (int u = 0; u < 8; u++)
#pragma unroll
                for (int v = 0; v < 8; v++)
                    acc[u][v] = fmaf(a[u], b[v], acc[u][v]);
        }
        __syncthreads();
    }

    float* out = g_Gp[blockIdx.z];
#pragma unroll
    for (int u = 0; u < 8; u++) {
        int row = i0 + ty * 8 + u;
        *(float4*)&out[(size_t)row * M_DIM + j0 + tx * 8] =
            make_float4(acc[u][0], acc[u][1], acc[u][2], acc[u][3]);
        *(float4*)&out[(size_t)row * M_DIM + j0 + tx * 8 + 4] =
            make_float4(acc[u][4], acc[u][5], acc[u][6], acc[u][7]);
    }
}

// ---------------------------------------------------------------- reduce: G = sum_z Gp[z]; residual partials
__global__ void __launch_bounds__(256) reduce_kernel() {
    if (g_done) return;
    const int idx = blockIdx.x * 256 + threadIdx.x;   // 65536 threads x 4 elems
    const int p = idx * 4;
    float4 s = make_float4(0.f, 0.f, 0.f, 0.f);
#pragma unroll
    for (int z = 0; z < SPLITK; z++) {
        float4 v = *(const float4*)&g_Gp[z][p];
        s.x += v.x; s.y += v.y; s.z += v.z; s.w += v.w;
    }
    *(float4*)&g_G[p] = s;
    const int row = p >> 9;       // p / 512
    const int col = p & 511;
    float e0 = ((row == col + 0) ? 1.f : 0.f) - s.x;
    float e1 = ((row == col + 1) ? 1.f : 0.f) - s.y;
    float e2 = ((row == col + 2) ? 1.f : 0.f) - s.z;
    float e3 = ((row == col + 3) ? 1.f : 0.f) - s.w;
    float local = e0 * e0 + e1 * e1 + e2 * e2 + e3 * e3;

    __shared__ float red[256];
    red[threadIdx.x] = local;
    __syncthreads();
    for (int off = 128; off > 0; off >>= 1) {
        if (threadIdx.x < off) red[threadIdx.x] += red[threadIdx.x + off];
        __syncthreads();
    }
    if (threadIdx.x == 0) g_rpart[blockIdx.x] = red[0];
}

// ---------------------------------------------------------------- check: set g_done if converged
__global__ void check_kernel(int step) {
    if (g_done) return;
    float s = 0.f;
    for (int i = threadIdx.x; i < 256; i += 32) s += g_rpart[i];
#pragma unroll
    for (int off = 16; off > 0; off >>= 1) s += __shfl_down_sync(0xffffffffu, s, off);
    if (threadIdx.x == 0 && step >= 1 && s <= EPS_F) g_done = 1;
}

// ---------------------------------------------------------------- update: X2 = X * (1.5I - 0.5G)
// grid (16,8): 128x64 output tile, K=512. 256 thr, 8x4 per thread.
__global__ void __launch_bounds__(256) update_kernel() {
    if (g_done) return;
    __shared__ float As[16][132];   // transposed X tile: As[k][row] (pad to dodge conflicts)
    __shared__ float Bs[16][64];    // W tile: Bs[k][col]
    const int i0 = blockIdx.x * 128;
    const int c0 = blockIdx.y * 64;
    const int tid = threadIdx.x;
    const int tx = tid & 15;
    const int ty = tid >> 4;

    float acc[8][4];
#pragma unroll
    for (int u = 0; u < 8; u++)
#pragma unroll
        for (int v = 0; v < 4; v++) acc[u][v] = 0.f;

    for (int k0 = 0; k0 < M_DIM; k0 += 16) {
        // A: 128 rows x 16 k, stored transposed
#pragma unroll
        for (int l = 0; l < 2; l++) {
            int id = tid + l * 256;       // 0..511 over 128 rows x 4 float4
            int r  = id >> 2;
            int kb = (id & 3) << 2;
            float4 v = *(const float4*)&g_X[(size_t)(i0 + r) * M_DIM + k0 + kb];
            As[kb + 0][r] = v.x;
            As[kb + 1][r] = v.y;
            As[kb + 2][r] = v.z;
            As[kb + 3][r] = v.w;
        }
        // B: 16 k x 64 cols, fold W = 1.5I - 0.5G on load
        {
            int r  = tid >> 4;            // 0..15
            int cb = (tid & 15) << 2;     // 0..60
            int grow = k0 + r;
            float4 v = *(const float4*)&g_G[(size_t)grow * M_DIM + c0 + cb];
            Bs[r][cb + 0] = ((grow == c0 + cb + 0) ? 1.5f : 0.f) - 0.5f * v.x;
            Bs[r][cb + 1] = ((grow == c0 + cb + 1) ? 1.5f : 0.f) - 0.5f * v.y;
            Bs[r][cb + 2] = ((grow == c0 + cb + 2) ? 1.5f : 0.f) - 0.5f * v.z;
            Bs[r][cb + 3] = ((grow == c0 + cb + 3) ? 1.5f : 0.f) - 0.5f * v.w;
        }
        __syncthreads();
#pragma unroll
        for (int kk = 0; kk < 16; kk++) {
            float a[8], b[4];
#pragma unroll
            for (int u = 0; u < 8; u++) a[u] = As[kk][ty * 8 + u];
#pragma unroll
            for (int v = 0; v < 4; v++) b[v] = Bs[kk][tx * 4 + v];
#pragma unroll
            for (int u = 0; u < 8; u++)
#pragma unroll
                for (int v = 0; v < 4; v++)
                    acc[u][v] = fmaf(a[u], b[v], acc[u][v]);
        }
        __syncthreads();
    }

#pragma unroll
    for (int u = 0; u < 8; u++) {
        int row = i0 + ty * 8 + u;
        *(float4*)&g_X2[(size_t)row * M_DIM + c0 + tx * 4] =
            make_float4(acc[u][0], acc[u][1], acc[u][2], acc[u][3]);
    }
}

// ---------------------------------------------------------------- copy back (skipped once converged)
__global__ void __launch_bounds__(256) copy_kernel() {
    if (g_done) return;
    int idx = blockIdx.x * blockDim.x + threadIdx.x;
    float4* dst = (float4*)g_X;
    const float4* src = (const float4*)g_X2;
    const int n4 = D_DIM * M_DIM / 4;
    for (int i = idx; i < n4; i += gridDim.x * blockDim.x) dst[i] = src[i];
}

// ---------------------------------------------------------------- emit result
__global__ void __launch_bounds__(256) final_kernel(float* __restrict__ out) {
    int idx = blockIdx.x * blockDim.x + threadIdx.x;
    float4* dst = (float4*)out;
    const float4* src = (const float4*)g_X;
    const int n4 = D_DIM * M_DIM / 4;
    for (int i = idx; i < n4; i += gridDim.x * blockDim.x) dst[i] = src[i];
}

extern "C" void kernel_launch(void* const* d_in, const int* in_sizes, int n_in,
                              void* d_out, int out_size) {
    const float* x = (const float*)d_in[0];
    float* out = (float*)d_out;
    (void)in_sizes; (void)n_in; (void)out_size;

    init_kernel<<<256, 256>>>(x);
    for (int k = 0; k < NSTEPS; k++) {
        gram_kernel<<<dim3(4, 4, SPLITK), 256>>>();
        reduce_kernel<<<256, 256>>>();
        check_kernel<<<1, 32>>>(k);
        update_kernel<<<dim3(16, 8), 256>>>();
        copy_kernel<<<256, 256>>>();
    }
    final_kernel<<<256, 256>>>(out);
}